// round 3
// baseline (speedup 1.0000x reference)
#include <cuda_runtime.h>
#include <math.h>

#define NU 100000
#define NI 50000
#define NE 120000
#define NR 32
#define DM 64
#define NEDGE 1000000
#define NCF 1000000

#define SEG_U 120000           // user segment base in global key space
#define SEG_I 220000           // item segment base
#define NSEG 270000
#define SCAN_N 270001
#define SCAN_BLK 1024
#define SCAN_NBLK 264          // 264*1024 = 270336 >= 270001

#define NCAP 48                // pairs whose rows are cached in smem
#define CCAP 256               // pairs whose col index is cached
#define SCAP 256               // pairs whose scalar p is cached

// ---------------- scratch (device globals; no allocation allowed) ----------------
__device__ int   g_cnt[SCAN_NBLK * SCAN_BLK];
__device__ int   g_off[SCAN_NBLK * SCAN_BLK + 1];
__device__ int   g_cur[NSEG];
__device__ int   g_perm[NEDGE + 2 * NCF];
__device__ int   g_bsum[SCAN_BLK];
__device__ int   g_boff[SCAN_BLK];

__device__ float g_entA[NE * DM];
__device__ float g_entB[NE * DM];
__device__ float g_rel[NI * DM];
__device__ float g_u[NU * DM];
__device__ float g_ucf0[NU * DM];
__device__ float g_ucf1[NU * DM];
__device__ float g_icf0[NI * DM];
__device__ float g_icf1[NI * DM];
__device__ float g_p[NCF];     // fallback scalar storage for huge segments
__device__ float g_pcf[NCF];

__device__ __forceinline__ float warpsum(float v) {
    #pragma unroll
    for (int o = 16; o; o >>= 1) v += __shfl_xor_sync(0xffffffffu, v, o);
    return v;
}
__device__ __forceinline__ float lrelu(float x) { return x > 0.f ? x : 0.01f * x; }
__device__ __forceinline__ float sigmoidf(float x) { return 1.f / (1.f + __expf(-x)); }

// ---------------- init: out = concat(entity, user, ucf, icf) ----------------
__global__ void k_init(const float* __restrict__ ue, const float* __restrict__ ee,
                       const float* __restrict__ cf, float* __restrict__ out) {
    const int total = (NE + NU + NU + NI) * DM;
    for (int i = blockIdx.x * blockDim.x + threadIdx.x; i < total; i += gridDim.x * blockDim.x) {
        float v;
        if (i < NE * DM)                   v = ee[i];
        else if (i < (NE + NU) * DM)       v = ue[i - NE * DM];
        else if (i < (NE + 2 * NU) * DM)   v = cf[i - (NE + NU) * DM];
        else                               v = cf[NU * DM + (i - (NE + 2 * NU) * DM)];
        out[i] = v;
    }
}

__global__ void k_zero() {
    for (int i = blockIdx.x * blockDim.x + threadIdx.x; i < SCAN_NBLK * SCAN_BLK;
         i += gridDim.x * blockDim.x) {
        g_cnt[i] = 0;
        if (i < NSEG) g_cur[i] = 0;
    }
}

__global__ void k_count(const int* __restrict__ heads, const int* __restrict__ imat) {
    for (int i = blockIdx.x * blockDim.x + threadIdx.x; i < NEDGE; i += gridDim.x * blockDim.x) {
        atomicAdd(&g_cnt[heads[i]], 1);
        atomicAdd(&g_cnt[SEG_U + imat[2 * i]], 1);
        atomicAdd(&g_cnt[SEG_I + imat[2 * i + 1]], 1);
    }
}

// ---------------- exclusive scan (3 phases) ----------------
__global__ void k_scan1() {
    __shared__ int sh[SCAN_BLK];
    int t = threadIdx.x;
    int i = blockIdx.x * SCAN_BLK + t;
    sh[t] = (i < SCAN_N) ? g_cnt[i] : 0;
    __syncthreads();
    for (int s = SCAN_BLK / 2; s > 0; s >>= 1) {
        if (t < s) sh[t] += sh[t + s];
        __syncthreads();
    }
    if (t == 0) g_bsum[blockIdx.x] = sh[0];
}
__global__ void k_scan2() {
    __shared__ int sh[SCAN_BLK];
    int t = threadIdx.x;
    int v = (t < SCAN_NBLK) ? g_bsum[t] : 0;
    sh[t] = v;
    __syncthreads();
    for (int d = 1; d < SCAN_BLK; d <<= 1) {
        int x = (t >= d) ? sh[t - d] : 0;
        __syncthreads();
        sh[t] += x;
        __syncthreads();
    }
    if (t < SCAN_NBLK) g_boff[t] = sh[t] - v;
}
__global__ void k_scan3() {
    __shared__ int sh[SCAN_BLK];
    int t = threadIdx.x;
    int i = blockIdx.x * SCAN_BLK + t;
    int v = (i < SCAN_N) ? g_cnt[i] : 0;
    sh[t] = v;
    __syncthreads();
    for (int d = 1; d < SCAN_BLK; d <<= 1) {
        int x = (t >= d) ? sh[t - d] : 0;
        __syncthreads();
        sh[t] += x;
        __syncthreads();
    }
    if (i < SCAN_N) g_off[i] = g_boff[blockIdx.x] + sh[t] - v;
}

__global__ void k_scatter(const int* __restrict__ heads, const int* __restrict__ imat) {
    for (int i = blockIdx.x * blockDim.x + threadIdx.x; i < NEDGE; i += gridDim.x * blockDim.x) {
        int h = heads[i];
        int p = g_off[h] + atomicAdd(&g_cur[h], 1);
        g_perm[p] = i;
        int r = SEG_U + imat[2 * i];
        p = g_off[r] + atomicAdd(&g_cur[r], 1);
        g_perm[p] = i;
        int c = SEG_I + imat[2 * i + 1];
        p = g_off[c] + atomicAdd(&g_cur[c], 1);
        g_perm[p] = i;
    }
}

// ---------------- entity aggregation + transform + norm + residual ----------------
__global__ void k_entity(const float* __restrict__ ext_ent, int hop,
                         const float* __restrict__ relw,
                         const float* __restrict__ W1, const float* __restrict__ b1,
                         const float* __restrict__ W2, const float* __restrict__ b2,
                         const int* __restrict__ tails, const int* __restrict__ etype,
                         float* __restrict__ out) {
    __shared__ float s_rel[NR * DM];
    __shared__ float sW1[DM * 65];
    __shared__ float sW2[DM * 65];
    __shared__ float sb1[DM], sb2[DM];
    int t = threadIdx.x;
    for (int i = t; i < NR * DM; i += blockDim.x) s_rel[i] = relw[i];
    for (int i = t; i < DM * DM; i += blockDim.x) {
        int d = i >> 6, k = i & 63;
        sW1[d * 65 + k] = W1[i];
        sW2[d * 65 + k] = W2[i];
    }
    if (t < DM) { sb1[t] = b1[t]; sb2[t] = b2[t]; }
    __syncthreads();

    const float* entin = hop ? g_entB : ext_ent;
    float* entout      = hop ? g_entA : g_entB;

    int lane = t & 31;
    int e = blockIdx.x * (blockDim.x >> 5) + (t >> 5);
    if (e >= NE) return;
    int p0 = g_off[e], p1 = g_off[e + 1];
    bool eItem = e < NI;

    float a10 = 0, a11 = 0, a20 = 0, a21 = 0, ar0 = 0, ar1 = 0;
    int nc = 0;
    for (int p = p0; p < p1; p++) {
        int eid = g_perm[p];
        int tl = tails[eid];
        int ty = etype[eid];
        float r0 = s_rel[ty * 64 + lane], r1 = s_rel[ty * 64 + 32 + lane];
        float t0 = entin[tl * 64 + lane], t1 = entin[tl * 64 + 32 + lane];
        bool cross = eItem != (tl < NI);
        if (cross) { a10 += t0 * r0; a11 += t1 * r1; nc++; }
        else       { a20 += t0 + r0; a21 += t1 + r1; }
        ar0 += r0; ar1 += r1;
    }
    int n = p1 - p0;
    float i1 = 1.f / fmaxf((float)nc, 1.f);
    float i2 = 1.f / fmaxf((float)(n - nc), 1.f);
    a10 *= i1; a11 *= i1; a20 *= i2; a21 *= i2;

    float o10 = sb1[lane], o11 = sb1[lane + 32];
    float o20 = sb2[lane], o21 = sb2[lane + 32];
    #pragma unroll
    for (int k = 0; k < 64; k++) {
        float a = __shfl_sync(0xffffffffu, (k < 32) ? a10 : a11, k & 31);
        o10 += a * sW1[lane * 65 + k];
        o11 += a * sW1[(lane + 32) * 65 + k];
    }
    #pragma unroll
    for (int k = 0; k < 64; k++) {
        float a = __shfl_sync(0xffffffffu, (k < 32) ? a20 : a21, k & 31);
        o20 += a * sW2[lane * 65 + k];
        o21 += a * sW2[(lane + 32) * 65 + k];
    }
    float v0 = 0.5f * (lrelu(o10) + lrelu(o20));
    float v1 = 0.5f * (lrelu(o11) + lrelu(o21));
    float ss = warpsum(v0 * v0 + v1 * v1);
    float inv = 1.f / fmaxf(sqrtf(ss), 1e-12f);
    v0 *= inv; v1 *= inv;
    entout[e * 64 + lane] = v0;
    entout[e * 64 + 32 + lane] = v1;
    out[e * 64 + lane] += v0;
    out[e * 64 + 32 + lane] += v1;
    if (eItem) {
        float dn = 1.f / fmaxf((float)n, 1.f);
        g_rel[e * 64 + lane] = ar0 * dn;
        g_rel[e * 64 + 32 + lane] = ar1 * dn;
    }
}

// ---------------- item aggregation (seg mean of ucf by col) ----------------
__global__ void k_item(const float* __restrict__ ext_ucf, int hop,
                       const int* __restrict__ imat, float* __restrict__ out) {
    const float* ucfin = hop ? g_ucf0 : ext_ucf;
    float* icfout      = hop ? g_icf1 : g_icf0;
    int t = threadIdx.x, lane = t & 31;
    int c = blockIdx.x * (blockDim.x >> 5) + (t >> 5);
    if (c >= NI) return;
    int p0 = g_off[SEG_I + c], p1 = g_off[SEG_I + c + 1];
    float a0 = 0, a1 = 0;
    for (int p = p0; p < p1; p++) {
        int pid = g_perm[p];
        int row = imat[2 * pid];
        a0 += ucfin[row * 64 + lane];
        a1 += ucfin[row * 64 + 32 + lane];
    }
    float dn = 1.f / fmaxf((float)(p1 - p0), 1.f);
    a0 *= dn; a1 *= dn;
    float ss = warpsum(a0 * a0 + a1 * a1);
    float inv = 1.f / fmaxf(sqrtf(ss), 1e-12f);
    a0 *= inv; a1 *= inv;
    icfout[c * 64 + lane] = a0;
    icfout[c * 64 + 32 + lane] = a1;
    const int ob = (NE + 2 * NU) * DM;
    out[ob + c * 64 + lane] += a0;
    out[ob + c * 64 + 32 + lane] += a1;
}

// ---------------- fused user kernel: 3 attention iterations, one hop ----------------
// One 128-thread block per user. Pair rows (r*k, k, i) cached in smem once;
// iterations 2,3 run entirely out of smem. Mask elided (provably always 1).
__global__ void __launch_bounds__(128) k_userhop(
        const float* __restrict__ ext_user, const float* __restrict__ ext_ucf,
        const float* __restrict__ ext_ent, const float* __restrict__ ext_icf,
        int hop, const int* __restrict__ imat, float* __restrict__ out)
{
    __shared__ float sK[NCAP * 64];   // (rel*kg) rows
    __shared__ float sG[NCAP * 64];   // kg rows
    __shared__ float sI[NCAP * 64];   // icf rows
    __shared__ float sS[SCAP], sSC[SCAP];
    __shared__ int   sCol[CCAP];
    __shared__ float sU[64], sUC[64];
    __shared__ float sRed[8];

    const float* kg     = hop ? g_entB : ext_ent;
    const float* icf    = hop ? g_icf0 : ext_icf;
    const float* usrc   = hop ? g_u    : ext_user;
    const float* ucfsrc = hop ? g_ucf0 : ext_ucf;
    float* ucfdst       = hop ? g_ucf1 : g_ucf0;

    int u = blockIdx.x;
    int t = threadIdx.x, lane = t & 31, wid = t >> 5;
    int p0 = g_off[SEG_U + u];
    int n  = g_off[SEG_U + u + 1] - p0;
    if (n == 0) {
        if (t < 64) g_u[u * 64 + t] = 0.f;
        else        ucfdst[u * 64 + (t - 64)] = 0.f;
        return;
    }
    int pb = p0 - NEDGE;   // user positions span [NEDGE, NEDGE+NCF)

    if (t < 64) sU[t] = usrc[u * 64 + t];
    else        sUC[t - 64] = ucfsrc[u * 64 + (t - 64)];
    __syncthreads();

    // ---- gather rows + iteration-0 dots ----
    for (int j = wid; j < n; j += 4) {
        int col;
        if (lane == 0) {
            int pid = g_perm[p0 + j];
            col = imat[2 * pid + 1];
            if (j < CCAP) sCol[j] = col;
        }
        col = __shfl_sync(0xffffffffu, col, 0);
        const float* kr = kg + col * 64;
        const float* rr = g_rel + col * 64;
        const float* ir = icf + col * 64;
        float k0 = kr[lane], k1 = kr[lane + 32];
        float r0 = rr[lane], r1 = rr[lane + 32];
        float i0 = ir[lane], i1 = ir[lane + 32];
        float K0 = r0 * k0, K1 = r1 * k1;
        if (j < NCAP) {
            sK[j * 64 + lane] = K0; sK[j * 64 + 32 + lane] = K1;
            sG[j * 64 + lane] = k0; sG[j * 64 + 32 + lane] = k1;
            sI[j * 64 + lane] = i0; sI[j * 64 + 32 + lane] = i1;
        }
        float s  = warpsum(sU[lane] * K0 + sU[lane + 32] * K1);
        float sc = warpsum(sUC[lane] * i0 + sUC[lane + 32] * i1);
        if (lane == 0) {
            if (j < SCAP) { sS[j] = s; sSC[j] = sc; }
            else          { g_p[pb + j] = s; g_pcf[pb + j] = sc; }
        }
    }

    for (int it = 0; it < 3; it++) {
        __syncthreads();
        // phase 1: max of sigmoid(dot)
        float m = -1e30f, mc = -1e30f;
        for (int j = t; j < n; j += 128) {
            float v  = (j < SCAP) ? sS[j]  : g_p[pb + j];
            float vc = (j < SCAP) ? sSC[j] : g_pcf[pb + j];
            m  = fmaxf(m,  sigmoidf(v));
            mc = fmaxf(mc, sigmoidf(vc));
        }
        #pragma unroll
        for (int o = 16; o; o >>= 1) {
            m  = fmaxf(m,  __shfl_xor_sync(0xffffffffu, m,  o));
            mc = fmaxf(mc, __shfl_xor_sync(0xffffffffu, mc, o));
        }
        if (lane == 0) { sRed[wid] = m; sRed[4 + wid] = mc; }
        __syncthreads();
        m  = fmaxf(fmaxf(sRed[0], sRed[1]), fmaxf(sRed[2], sRed[3]));
        mc = fmaxf(fmaxf(sRed[4], sRed[5]), fmaxf(sRed[6], sRed[7]));
        __syncthreads();
        // phase 2: exp + sum, store e in place
        float se = 0.f, sec = 0.f;
        for (int j = t; j < n; j += 128) {
            float v  = (j < SCAP) ? sS[j]  : g_p[pb + j];
            float vc = (j < SCAP) ? sSC[j] : g_pcf[pb + j];
            float e  = __expf(sigmoidf(v)  - m);
            float ec = __expf(sigmoidf(vc) - mc);
            if (j < SCAP) { sS[j] = e; sSC[j] = ec; }
            else          { g_p[pb + j] = e; g_pcf[pb + j] = ec; }
            se += e; sec += ec;
        }
        se = warpsum(se); sec = warpsum(sec);
        if (lane == 0) { sRed[wid] = se; sRed[4 + wid] = sec; }
        __syncthreads();
        float inv  = 1.f / (sRed[0] + sRed[1] + sRed[2] + sRed[3]);
        float invc = 1.f / (sRed[4] + sRed[5] + sRed[6] + sRed[7]);
        // phase 3: weighted accumulation (u' and ucf')
        float acc = 0.f;
        if (t < 64) {
            for (int j = 0; j < n; j++) {
                float w = ((j < SCAP) ? sS[j] : g_p[pb + j]) * inv;
                float gv;
                if (j < NCAP) gv = sG[j * 64 + t];
                else {
                    int col = (j < CCAP) ? sCol[j] : imat[2 * g_perm[p0 + j] + 1];
                    gv = kg[col * 64 + t];
                }
                acc += w * gv;
            }
        } else {
            int d = t - 64;
            for (int j = 0; j < n; j++) {
                float w = ((j < SCAP) ? sSC[j] : g_pcf[pb + j]) * invc;
                float iv;
                if (j < NCAP) iv = sI[j * 64 + d];
                else {
                    int col = (j < CCAP) ? sCol[j] : imat[2 * g_perm[p0 + j] + 1];
                    iv = icf[col * 64 + d];
                }
                acc += w * iv;
            }
        }
        __syncthreads();
        if (t < 64) sU[t] = acc; else sUC[t - 64] = acc;
        __syncthreads();
        // norms (warp0: u, warp1: ucf)
        if (wid == 0) {
            float a = sU[lane], b = sU[lane + 32];
            float ss = warpsum(a * a + b * b);
            if (lane == 0) sRed[0] = 1.f / fmaxf(sqrtf(ss), 1e-12f);
        } else if (wid == 1) {
            float a = sUC[lane], b = sUC[lane + 32];
            float ss = warpsum(a * a + b * b);
            if (lane == 0) sRed[1] = 1.f / fmaxf(sqrtf(ss), 1e-12f);
        }
        __syncthreads();
        if (t < 64) sU[t] *= sRed[0]; else sUC[t - 64] *= sRed[1];
        // next-iteration dots (pure smem for cached pairs)
        if (it < 2) {
            __syncthreads();
            for (int j = wid; j < n; j += 4) {
                float K0, K1, i0, i1;
                if (j < NCAP) {
                    K0 = sK[j * 64 + lane]; K1 = sK[j * 64 + 32 + lane];
                    i0 = sI[j * 64 + lane]; i1 = sI[j * 64 + 32 + lane];
                } else {
                    int col;
                    if (lane == 0) col = (j < CCAP) ? sCol[j] : imat[2 * g_perm[p0 + j] + 1];
                    col = __shfl_sync(0xffffffffu, col, 0);
                    float k0 = kg[col * 64 + lane], k1 = kg[col * 64 + lane + 32];
                    K0 = g_rel[col * 64 + lane] * k0;
                    K1 = g_rel[col * 64 + lane + 32] * k1;
                    i0 = icf[col * 64 + lane]; i1 = icf[col * 64 + lane + 32];
                }
                float s  = warpsum(sU[lane] * K0 + sU[lane + 32] * K1);
                float sc = warpsum(sUC[lane] * i0 + sUC[lane + 32] * i1);
                if (lane == 0) {
                    if (j < SCAP) { sS[j] = s; sSC[j] = sc; }
                    else          { g_p[pb + j] = s; g_pcf[pb + j] = sc; }
                }
            }
        }
    }

    // final writes: state for next hop + residual into out
    if (t < 64) {
        g_u[u * 64 + t] = sU[t];
        out[NE * DM + u * 64 + t] += sU[t];
    } else {
        int d = t - 64;
        ucfdst[u * 64 + d] = sUC[d];
        out[(NE + NU) * DM + u * 64 + d] += sUC[d];
    }
}

// ---------------- launch ----------------
extern "C" void kernel_launch(void* const* d_in, const int* in_sizes, int n_in,
                              void* d_out, int out_size) {
    const float* user_emb = (const float*)d_in[0];
    const float* entity_emb = (const float*)d_in[1];
    const float* emb_cf = (const float*)d_in[2];
    const float* relw = (const float*)d_in[3];
    const float* W1 = (const float*)d_in[4];
    const float* B1 = (const float*)d_in[5];
    const float* W2 = (const float*)d_in[6];
    const float* B2 = (const float*)d_in[7];
    const int* eidx = (const int*)d_in[8];       // (2, NEDGE)
    const int* etype = (const int*)d_in[9];
    const int* imat = (const int*)d_in[10];      // (NCF, 2)
    float* out = (float*)d_out;

    const int* heads = eidx;
    const int* tails = eidx + NEDGE;
    const float* ucf_ext = emb_cf;               // first NU rows
    const float* icf_ext = emb_cf + NU * DM;     // last NI rows

    k_init<<<2048, 256>>>(user_emb, entity_emb, emb_cf, out);
    k_zero<<<1056, 256>>>();
    k_count<<<3907, 256>>>(heads, imat);
    k_scan1<<<SCAN_NBLK, SCAN_BLK>>>();
    k_scan2<<<1, SCAN_BLK>>>();
    k_scan3<<<SCAN_NBLK, SCAN_BLK>>>();
    k_scatter<<<3907, 256>>>(heads, imat);

    for (int h = 0; h < 2; h++) {
        k_entity<<<NE / 8, 256>>>(entity_emb, h, relw,
                                  W1 + h * DM * DM, B1 + h * DM,
                                  W2 + h * DM * DM, B2 + h * DM,
                                  tails, etype, out);
        k_item<<<NI / 8, 256>>>(ucf_ext, h, imat, out);
        k_userhop<<<NU, 128>>>(user_emb, ucf_ext, entity_emb, icf_ext,
                               h, imat, out);
    }
    (void)in_sizes; (void)n_in; (void)out_size;
}

// round 4
// speedup vs baseline: 1.2320x; 1.2320x over previous
#include <cuda_runtime.h>
#include <math.h>

#define NU 100000
#define NI 50000
#define NE 120000
#define NR 32
#define DM 64
#define NEDGE 1000000
#define NCF 1000000

#define SEG_U 120000
#define SEG_I 220000
#define NSEG 270000
#define SCAN_N 270001
#define SCAN_BLK 1024
#define SCAN_NBLK 264

__device__ int   g_cnt[SCAN_NBLK * SCAN_BLK];
__device__ int   g_off[SCAN_NBLK * SCAN_BLK + 1];
__device__ int   g_cur[NSEG];
__device__ int   g_perm[NEDGE + 2 * NCF];
__device__ int   g_bsum[SCAN_BLK];
__device__ int   g_boff[SCAN_BLK];

__device__ float g_entA[NE * DM];
__device__ float g_entB[NE * DM];
__device__ float g_rel[NI * DM];
__device__ float g_relkg[NI * DM];
__device__ float g_u[NU * DM];
__device__ float g_ucf0[NU * DM];
__device__ float g_ucf1[NU * DM];
__device__ float g_icf0[NI * DM];
__device__ float g_icf1[NI * DM];
__device__ float g_p[NCF];
__device__ float g_pcf[NCF];

__device__ __forceinline__ float warpsum(float v) {
    #pragma unroll
    for (int o = 16; o; o >>= 1) v += __shfl_xor_sync(0xffffffffu, v, o);
    return v;
}
__device__ __forceinline__ float lrelu(float x) { return x > 0.f ? x : 0.01f * x; }
__device__ __forceinline__ float sigmoidf(float x) { return 1.f / (1.f + __expf(-x)); }

__global__ void k_init(const float* __restrict__ ue, const float* __restrict__ ee,
                       const float* __restrict__ cf, float* __restrict__ out) {
    const int total = (NE + NU + NU + NI) * DM;
    for (int i = blockIdx.x * blockDim.x + threadIdx.x; i < total; i += gridDim.x * blockDim.x) {
        float v;
        if (i < NE * DM)                   v = ee[i];
        else if (i < (NE + NU) * DM)       v = ue[i - NE * DM];
        else if (i < (NE + 2 * NU) * DM)   v = cf[i - (NE + NU) * DM];
        else                               v = cf[NU * DM + (i - (NE + 2 * NU) * DM)];
        out[i] = v;
    }
}

__global__ void k_zero() {
    for (int i = blockIdx.x * blockDim.x + threadIdx.x; i < SCAN_NBLK * SCAN_BLK;
         i += gridDim.x * blockDim.x) {
        g_cnt[i] = 0;
        if (i < NSEG) g_cur[i] = 0;
    }
}

__global__ void k_count(const int* __restrict__ heads, const int* __restrict__ imat) {
    for (int i = blockIdx.x * blockDim.x + threadIdx.x; i < NEDGE; i += gridDim.x * blockDim.x) {
        atomicAdd(&g_cnt[heads[i]], 1);
        atomicAdd(&g_cnt[SEG_U + imat[2 * i]], 1);
        atomicAdd(&g_cnt[SEG_I + imat[2 * i + 1]], 1);
    }
}

__global__ void k_scan1() {
    __shared__ int sh[SCAN_BLK];
    int t = threadIdx.x;
    int i = blockIdx.x * SCAN_BLK + t;
    sh[t] = (i < SCAN_N) ? g_cnt[i] : 0;
    __syncthreads();
    for (int s = SCAN_BLK / 2; s > 0; s >>= 1) {
        if (t < s) sh[t] += sh[t + s];
        __syncthreads();
    }
    if (t == 0) g_bsum[blockIdx.x] = sh[0];
}
__global__ void k_scan2() {
    __shared__ int sh[SCAN_BLK];
    int t = threadIdx.x;
    int v = (t < SCAN_NBLK) ? g_bsum[t] : 0;
    sh[t] = v;
    __syncthreads();
    for (int d = 1; d < SCAN_BLK; d <<= 1) {
        int x = (t >= d) ? sh[t - d] : 0;
        __syncthreads();
        sh[t] += x;
        __syncthreads();
    }
    if (t < SCAN_NBLK) g_boff[t] = sh[t] - v;
}
__global__ void k_scan3() {
    __shared__ int sh[SCAN_BLK];
    int t = threadIdx.x;
    int i = blockIdx.x * SCAN_BLK + t;
    int v = (i < SCAN_N) ? g_cnt[i] : 0;
    sh[t] = v;
    __syncthreads();
    for (int d = 1; d < SCAN_BLK; d <<= 1) {
        int x = (t >= d) ? sh[t - d] : 0;
        __syncthreads();
        sh[t] += x;
        __syncthreads();
    }
    if (i < SCAN_N) g_off[i] = g_boff[blockIdx.x] + sh[t] - v;
}

__global__ void k_scatter(const int* __restrict__ heads, const int* __restrict__ imat) {
    for (int i = blockIdx.x * blockDim.x + threadIdx.x; i < NEDGE; i += gridDim.x * blockDim.x) {
        int h = heads[i];
        int p = g_off[h] + atomicAdd(&g_cur[h], 1);
        g_perm[p] = i;
        int r = SEG_U + imat[2 * i];
        p = g_off[r] + atomicAdd(&g_cur[r], 1);
        g_perm[p] = i;
        int c = SEG_I + imat[2 * i + 1];
        p = g_off[c] + atomicAdd(&g_cur[c], 1);
        g_perm[p] = i;
    }
}

__global__ void k_entity(const float* __restrict__ ext_ent, int hop,
                         const float* __restrict__ relw,
                         const float* __restrict__ W1, const float* __restrict__ b1,
                         const float* __restrict__ W2, const float* __restrict__ b2,
                         const int* __restrict__ tails, const int* __restrict__ etype,
                         float* __restrict__ out) {
    __shared__ float s_rel[NR * DM];
    __shared__ float sW1[DM * 65];
    __shared__ float sW2[DM * 65];
    __shared__ float sb1[DM], sb2[DM];
    int t = threadIdx.x;
    for (int i = t; i < NR * DM; i += blockDim.x) s_rel[i] = relw[i];
    for (int i = t; i < DM * DM; i += blockDim.x) {
        int d = i >> 6, k = i & 63;
        sW1[d * 65 + k] = W1[i];
        sW2[d * 65 + k] = W2[i];
    }
    if (t < DM) { sb1[t] = b1[t]; sb2[t] = b2[t]; }
    __syncthreads();

    const float* entin = hop ? g_entB : ext_ent;
    float* entout      = hop ? g_entA : g_entB;

    int lane = t & 31;
    int e = blockIdx.x * (blockDim.x >> 5) + (t >> 5);
    if (e >= NE) return;
    int p0 = g_off[e], p1 = g_off[e + 1];
    bool eItem = e < NI;

    float a10 = 0, a11 = 0, a20 = 0, a21 = 0, ar0 = 0, ar1 = 0;
    int nc = 0;
    for (int p = p0; p < p1; p++) {
        int eid = g_perm[p];
        int tl = tails[eid];
        int ty = etype[eid];
        float r0 = s_rel[ty * 64 + lane], r1 = s_rel[ty * 64 + 32 + lane];
        float t0 = entin[tl * 64 + lane], t1 = entin[tl * 64 + 32 + lane];
        bool cross = eItem != (tl < NI);
        if (cross) { a10 += t0 * r0; a11 += t1 * r1; nc++; }
        else       { a20 += t0 + r0; a21 += t1 + r1; }
        ar0 += r0; ar1 += r1;
    }
    int n = p1 - p0;
    float i1 = 1.f / fmaxf((float)nc, 1.f);
    float i2 = 1.f / fmaxf((float)(n - nc), 1.f);
    a10 *= i1; a11 *= i1; a20 *= i2; a21 *= i2;

    float o10 = sb1[lane], o11 = sb1[lane + 32];
    float o20 = sb2[lane], o21 = sb2[lane + 32];
    #pragma unroll
    for (int k = 0; k < 64; k++) {
        float a = __shfl_sync(0xffffffffu, (k < 32) ? a10 : a11, k & 31);
        o10 += a * sW1[lane * 65 + k];
        o11 += a * sW1[(lane + 32) * 65 + k];
    }
    #pragma unroll
    for (int k = 0; k < 64; k++) {
        float a = __shfl_sync(0xffffffffu, (k < 32) ? a20 : a21, k & 31);
        o20 += a * sW2[lane * 65 + k];
        o21 += a * sW2[(lane + 32) * 65 + k];
    }
    float v0 = 0.5f * (lrelu(o10) + lrelu(o20));
    float v1 = 0.5f * (lrelu(o11) + lrelu(o21));
    float ss = warpsum(v0 * v0 + v1 * v1);
    float inv = 1.f / fmaxf(sqrtf(ss), 1e-12f);
    v0 *= inv; v1 *= inv;
    entout[e * 64 + lane] = v0;
    entout[e * 64 + 32 + lane] = v1;
    out[e * 64 + lane] += v0;
    out[e * 64 + 32 + lane] += v1;
    if (eItem) {
        float dn = 1.f / fmaxf((float)n, 1.f);
        g_rel[e * 64 + lane] = ar0 * dn;
        g_rel[e * 64 + 32 + lane] = ar1 * dn;
    }
}

// relkg = rel * kg (item rows); kg resolved device-side from hop flag
__global__ void k_relkg(const float* __restrict__ ext_ent, int hop) {
    const float* kgbase = hop ? g_entB : ext_ent;
    int i = blockIdx.x * blockDim.x + threadIdx.x;
    if (i < NI * DM) g_relkg[i] = g_rel[i] * kgbase[i];
}

__global__ void k_item(const float* __restrict__ ext_ucf, int hop,
                       const int* __restrict__ imat, float* __restrict__ out) {
    const float* ucfin = hop ? g_ucf0 : ext_ucf;
    float* icfout      = hop ? g_icf1 : g_icf0;
    int t = threadIdx.x, lane = t & 31;
    int c = blockIdx.x * (blockDim.x >> 5) + (t >> 5);
    if (c >= NI) return;
    int p0 = g_off[SEG_I + c], p1 = g_off[SEG_I + c + 1];
    float a0 = 0, a1 = 0;
    for (int p = p0; p < p1; p++) {
        int pid = g_perm[p];
        int row = imat[2 * pid];
        a0 += ucfin[row * 64 + lane];
        a1 += ucfin[row * 64 + 32 + lane];
    }
    float dn = 1.f / fmaxf((float)(p1 - p0), 1.f);
    a0 *= dn; a1 *= dn;
    float ss = warpsum(a0 * a0 + a1 * a1);
    float inv = 1.f / fmaxf(sqrtf(ss), 1e-12f);
    a0 *= inv; a1 *= inv;
    icfout[c * 64 + lane] = a0;
    icfout[c * 64 + 32 + lane] = a1;
    const int ob = (NE + 2 * NU) * DM;
    out[ob + c * 64 + lane] += a0;
    out[ob + c * 64 + 32 + lane] += a1;
}

// fused user kernel: warp per user, 3 iterations, register softmax
__global__ void __launch_bounds__(256) k_userhop(
        const float* __restrict__ ext_user, const float* __restrict__ ext_ucf,
        const float* __restrict__ ext_ent, const float* __restrict__ ext_icf,
        int hop, const int* __restrict__ imat, float* __restrict__ out)
{
    const float2* kg2     = (const float2*)(hop ? g_entB : ext_ent);
    const float2* icf2    = (const float2*)(hop ? g_icf0 : ext_icf);
    const float2* rk2     = (const float2*)g_relkg;
    const float2* usrc2   = (const float2*)(hop ? g_u    : ext_user);
    const float2* ucfsrc2 = (const float2*)(hop ? g_ucf0 : ext_ucf);
    float2* udst2   = (float2*)g_u;
    float2* ucfdst2 = (float2*)(hop ? g_ucf1 : g_ucf0);
    float2* out2    = (float2*)out;

    int u = blockIdx.x * 8 + (threadIdx.x >> 5);
    if (u >= NU) return;
    int lane = threadIdx.x & 31;
    int p0 = g_off[SEG_U + u];
    int n  = g_off[SEG_U + u + 1] - p0;
    if (n == 0) {
        float2 z = make_float2(0.f, 0.f);
        udst2[u * 32 + lane] = z;
        ucfdst2[u * 32 + lane] = z;
        return;
    }
    int pb = p0 - NEDGE;
    int nin = n < 64 ? n : 64;

    float2 ud = usrc2[u * 32 + lane];
    float2 cd = ucfsrc2[u * 32 + lane];

    int colA = 0, colB = 0;
    if (lane < n)      colA = imat[2 * g_perm[p0 + lane] + 1];
    if (lane + 32 < n) colB = imat[2 * g_perm[p0 + lane + 32] + 1];
    bool vA = lane < n;
    bool vB = (lane + 32) < n;

    for (int it = 0; it < 3; it++) {
        float sA = -1e30f, sB = -1e30f, cAs = -1e30f, cBs = -1e30f;
        for (int j = 0; j < nin; j++) {
            int col = __shfl_sync(0xffffffffu, (j < 32) ? colA : colB, j & 31);
            float2 rk = rk2[col * 32 + lane];
            float2 iv = icf2[col * 32 + lane];
            float s  = warpsum(ud.x * rk.x + ud.y * rk.y);
            float sc = warpsum(cd.x * iv.x + cd.y * iv.y);
            if (lane == (j & 31)) {
                if (j < 32) { sA = s; cAs = sc; }
                else        { sB = s; cBs = sc; }
            }
        }
        for (int j = 64; j < n; j++) {
            int col = imat[2 * g_perm[p0 + j] + 1];
            float2 rk = rk2[col * 32 + lane];
            float2 iv = icf2[col * 32 + lane];
            float s  = warpsum(ud.x * rk.x + ud.y * rk.y);
            float sc = warpsum(cd.x * iv.x + cd.y * iv.y);
            if (lane == 0) { g_p[pb + j] = s; g_pcf[pb + j] = sc; }
        }
        float m = fmaxf(sA, sB), mc = fmaxf(cAs, cBs);
        for (int j = 64 + lane; j < n; j += 32) {
            m = fmaxf(m, g_p[pb + j]); mc = fmaxf(mc, g_pcf[pb + j]);
        }
        #pragma unroll
        for (int o = 16; o; o >>= 1) {
            m  = fmaxf(m,  __shfl_xor_sync(0xffffffffu, m,  o));
            mc = fmaxf(mc, __shfl_xor_sync(0xffffffffu, mc, o));
        }
        m = sigmoidf(m); mc = sigmoidf(mc);
        float eA  = vA ? __expf(sigmoidf(sA)  - m)  : 0.f;
        float eB  = vB ? __expf(sigmoidf(sB)  - m)  : 0.f;
        float ecA = vA ? __expf(sigmoidf(cAs) - mc) : 0.f;
        float ecB = vB ? __expf(sigmoidf(cBs) - mc) : 0.f;
        float se = eA + eB, sec = ecA + ecB;
        for (int j = 64 + lane; j < n; j += 32) {
            float e  = __expf(sigmoidf(g_p[pb + j])   - m);
            float ec = __expf(sigmoidf(g_pcf[pb + j]) - mc);
            g_p[pb + j] = e; g_pcf[pb + j] = ec;
            se += e; sec += ec;
        }
        se = warpsum(se); sec = warpsum(sec);
        float inv = 1.f / se, invc = 1.f / sec;
        float2 A = make_float2(0.f, 0.f), B = make_float2(0.f, 0.f);
        for (int j = 0; j < nin; j++) {
            float e   = __shfl_sync(0xffffffffu, (j < 32) ? eA  : eB,  j & 31);
            float ec  = __shfl_sync(0xffffffffu, (j < 32) ? ecA : ecB, j & 31);
            int col   = __shfl_sync(0xffffffffu, (j < 32) ? colA : colB, j & 31);
            float2 gv = kg2[col * 32 + lane];
            float2 iv = icf2[col * 32 + lane];
            float wp = e * inv, wc = ec * invc;
            A.x += wp * gv.x; A.y += wp * gv.y;
            B.x += wc * iv.x; B.y += wc * iv.y;
        }
        for (int j = 64; j < n; j++) {
            float wp = g_p[pb + j] * inv, wc = g_pcf[pb + j] * invc;
            int col = imat[2 * g_perm[p0 + j] + 1];
            float2 gv = kg2[col * 32 + lane];
            float2 iv = icf2[col * 32 + lane];
            A.x += wp * gv.x; A.y += wp * gv.y;
            B.x += wc * iv.x; B.y += wc * iv.y;
        }
        float ss = warpsum(A.x * A.x + A.y * A.y);
        float i1 = 1.f / fmaxf(sqrtf(ss), 1e-12f);
        ss = warpsum(B.x * B.x + B.y * B.y);
        float i2 = 1.f / fmaxf(sqrtf(ss), 1e-12f);
        ud.x = A.x * i1; ud.y = A.y * i1;
        cd.x = B.x * i2; cd.y = B.y * i2;
    }

    udst2[u * 32 + lane] = ud;
    ucfdst2[u * 32 + lane] = cd;
    int o1 = NE * 32 + u * 32 + lane;
    float2 o = out2[o1]; o.x += ud.x; o.y += ud.y; out2[o1] = o;
    int o2 = (NE + NU) * 32 + u * 32 + lane;
    o = out2[o2]; o.x += cd.x; o.y += cd.y; out2[o2] = o;
}

extern "C" void kernel_launch(void* const* d_in, const int* in_sizes, int n_in,
                              void* d_out, int out_size) {
    const float* user_emb = (const float*)d_in[0];
    const float* entity_emb = (const float*)d_in[1];
    const float* emb_cf = (const float*)d_in[2];
    const float* relw = (const float*)d_in[3];
    const float* W1 = (const float*)d_in[4];
    const float* B1 = (const float*)d_in[5];
    const float* W2 = (const float*)d_in[6];
    const float* B2 = (const float*)d_in[7];
    const int* eidx = (const int*)d_in[8];
    const int* etype = (const int*)d_in[9];
    const int* imat = (const int*)d_in[10];
    float* out = (float*)d_out;

    const int* heads = eidx;
    const int* tails = eidx + NEDGE;
    const float* ucf_ext = emb_cf;
    const float* icf_ext = emb_cf + NU * DM;

    k_init<<<2048, 256>>>(user_emb, entity_emb, emb_cf, out);
    k_zero<<<1056, 256>>>();
    k_count<<<3907, 256>>>(heads, imat);
    k_scan1<<<SCAN_NBLK, SCAN_BLK>>>();
    k_scan2<<<1, SCAN_BLK>>>();
    k_scan3<<<SCAN_NBLK, SCAN_BLK>>>();
    k_scatter<<<3907, 256>>>(heads, imat);

    for (int h = 0; h < 2; h++) {
        k_entity<<<NE / 8, 256>>>(entity_emb, h, relw,
                                  W1 + h * DM * DM, B1 + h * DM,
                                  W2 + h * DM * DM, B2 + h * DM,
                                  tails, etype, out);
        k_relkg<<<(NI * DM + 255) / 256, 256>>>(entity_emb, h);
        k_item<<<NI / 8, 256>>>(ucf_ext, h, imat, out);
        k_userhop<<<(NU + 7) / 8, 256>>>(user_emb, ucf_ext, entity_emb, icf_ext,
                                         h, imat, out);
    }
    (void)in_sizes; (void)n_in; (void)out_size;
}

// round 5
// speedup vs baseline: 2.3093x; 1.8744x over previous
#include <cuda_runtime.h>
#include <math.h>

#define NU 100000
#define NI 50000
#define NE 120000
#define NR 32
#define DM 64
#define NEDGE 1000000
#define NCF 1000000

#define SEG_U 120000
#define SEG_I 220000
#define NSEG 270000
#define SCAN_N 270001
#define SCAN_BLK 1024
#define SCAN_NBLK 264

__device__ int   g_cnt[SCAN_NBLK * SCAN_BLK];
__device__ int   g_off[SCAN_NBLK * SCAN_BLK + 1];
__device__ int   g_cur[NSEG];
__device__ int   g_perm[NEDGE + 2 * NCF];
__device__ int   g_bsum[SCAN_BLK];
__device__ int   g_boff[SCAN_BLK];

__device__ float g_entA[NE * DM];
__device__ float g_entB[NE * DM];
__device__ float g_rel[NI * DM];
__device__ float g_relkg[NI * DM];
__device__ float g_u[NU * DM];
__device__ float g_ucf0[NU * DM];
__device__ float g_ucf1[NU * DM];
__device__ float g_icf0[NI * DM];
__device__ float g_icf1[NI * DM];
__device__ float g_p[NCF];
__device__ float g_pcf[NCF];

__device__ __forceinline__ float warpsum(float v) {
    #pragma unroll
    for (int o = 16; o; o >>= 1) v += __shfl_xor_sync(0xffffffffu, v, o);
    return v;
}
__device__ __forceinline__ float lrelu(float x) { return x > 0.f ? x : 0.01f * x; }
__device__ __forceinline__ float sigmoidf(float x) { return 1.f / (1.f + __expf(-x)); }

__global__ void k_init(const float* __restrict__ ue, const float* __restrict__ ee,
                       const float* __restrict__ cf, float* __restrict__ out) {
    const int total = (NE + NU + NU + NI) * DM;
    for (int i = blockIdx.x * blockDim.x + threadIdx.x; i < total; i += gridDim.x * blockDim.x) {
        float v;
        if (i < NE * DM)                   v = ee[i];
        else if (i < (NE + NU) * DM)       v = ue[i - NE * DM];
        else if (i < (NE + 2 * NU) * DM)   v = cf[i - (NE + NU) * DM];
        else                               v = cf[NU * DM + (i - (NE + 2 * NU) * DM)];
        out[i] = v;
    }
}

__global__ void k_zero() {
    for (int i = blockIdx.x * blockDim.x + threadIdx.x; i < SCAN_NBLK * SCAN_BLK;
         i += gridDim.x * blockDim.x) {
        g_cnt[i] = 0;
        if (i < NSEG) g_cur[i] = 0;
    }
}

__global__ void k_count(const int* __restrict__ heads, const int* __restrict__ imat) {
    for (int i = blockIdx.x * blockDim.x + threadIdx.x; i < NEDGE; i += gridDim.x * blockDim.x) {
        atomicAdd(&g_cnt[heads[i]], 1);
        atomicAdd(&g_cnt[SEG_U + imat[2 * i]], 1);
        atomicAdd(&g_cnt[SEG_I + imat[2 * i + 1]], 1);
    }
}

__global__ void k_scan1() {
    __shared__ int sh[SCAN_BLK];
    int t = threadIdx.x;
    int i = blockIdx.x * SCAN_BLK + t;
    sh[t] = (i < SCAN_N) ? g_cnt[i] : 0;
    __syncthreads();
    for (int s = SCAN_BLK / 2; s > 0; s >>= 1) {
        if (t < s) sh[t] += sh[t + s];
        __syncthreads();
    }
    if (t == 0) g_bsum[blockIdx.x] = sh[0];
}
__global__ void k_scan2() {
    __shared__ int sh[SCAN_BLK];
    int t = threadIdx.x;
    int v = (t < SCAN_NBLK) ? g_bsum[t] : 0;
    sh[t] = v;
    __syncthreads();
    for (int d = 1; d < SCAN_BLK; d <<= 1) {
        int x = (t >= d) ? sh[t - d] : 0;
        __syncthreads();
        sh[t] += x;
        __syncthreads();
    }
    if (t < SCAN_NBLK) g_boff[t] = sh[t] - v;
}
__global__ void k_scan3() {
    __shared__ int sh[SCAN_BLK];
    int t = threadIdx.x;
    int i = blockIdx.x * SCAN_BLK + t;
    int v = (i < SCAN_N) ? g_cnt[i] : 0;
    sh[t] = v;
    __syncthreads();
    for (int d = 1; d < SCAN_BLK; d <<= 1) {
        int x = (t >= d) ? sh[t - d] : 0;
        __syncthreads();
        sh[t] += x;
        __syncthreads();
    }
    if (i < SCAN_N) g_off[i] = g_boff[blockIdx.x] + sh[t] - v;
}

__global__ void k_scatter(const int* __restrict__ heads, const int* __restrict__ imat) {
    for (int i = blockIdx.x * blockDim.x + threadIdx.x; i < NEDGE; i += gridDim.x * blockDim.x) {
        int h = heads[i];
        int p = g_off[h] + atomicAdd(&g_cur[h], 1);
        g_perm[p] = i;
        int r = SEG_U + imat[2 * i];
        p = g_off[r] + atomicAdd(&g_cur[r], 1);
        g_perm[p] = i;
        int c = SEG_I + imat[2 * i + 1];
        p = g_off[c] + atomicAdd(&g_cur[c], 1);
        g_perm[p] = i;
    }
}

__global__ void k_entity(const float* __restrict__ ext_ent, int hop,
                         const float* __restrict__ relw,
                         const float* __restrict__ W1, const float* __restrict__ b1,
                         const float* __restrict__ W2, const float* __restrict__ b2,
                         const int* __restrict__ tails, const int* __restrict__ etype,
                         float* __restrict__ out) {
    __shared__ float s_rel[NR * DM];
    __shared__ float sW1[DM * 65];
    __shared__ float sW2[DM * 65];
    __shared__ float sb1[DM], sb2[DM];
    int t = threadIdx.x;
    for (int i = t; i < NR * DM; i += blockDim.x) s_rel[i] = relw[i];
    for (int i = t; i < DM * DM; i += blockDim.x) {
        int d = i >> 6, k = i & 63;
        sW1[d * 65 + k] = W1[i];
        sW2[d * 65 + k] = W2[i];
    }
    if (t < DM) { sb1[t] = b1[t]; sb2[t] = b2[t]; }
    __syncthreads();

    const float* entin = hop ? g_entB : ext_ent;
    float* entout      = hop ? g_entA : g_entB;

    int lane = t & 31;
    int e = blockIdx.x * (blockDim.x >> 5) + (t >> 5);
    if (e >= NE) return;
    int p0 = g_off[e], p1 = g_off[e + 1];
    bool eItem = e < NI;

    float a10 = 0, a11 = 0, a20 = 0, a21 = 0, ar0 = 0, ar1 = 0;
    int nc = 0;
    for (int p = p0; p < p1; p++) {
        int eid = g_perm[p];
        int tl = tails[eid];
        int ty = etype[eid];
        float r0 = s_rel[ty * 64 + lane], r1 = s_rel[ty * 64 + 32 + lane];
        float t0 = entin[tl * 64 + lane], t1 = entin[tl * 64 + 32 + lane];
        bool cross = eItem != (tl < NI);
        if (cross) { a10 += t0 * r0; a11 += t1 * r1; nc++; }
        else       { a20 += t0 + r0; a21 += t1 + r1; }
        ar0 += r0; ar1 += r1;
    }
    int n = p1 - p0;
    float i1 = 1.f / fmaxf((float)nc, 1.f);
    float i2 = 1.f / fmaxf((float)(n - nc), 1.f);
    a10 *= i1; a11 *= i1; a20 *= i2; a21 *= i2;

    float o10 = sb1[lane], o11 = sb1[lane + 32];
    float o20 = sb2[lane], o21 = sb2[lane + 32];
    #pragma unroll
    for (int k = 0; k < 64; k++) {
        float a = __shfl_sync(0xffffffffu, (k < 32) ? a10 : a11, k & 31);
        o10 += a * sW1[lane * 65 + k];
        o11 += a * sW1[(lane + 32) * 65 + k];
    }
    #pragma unroll
    for (int k = 0; k < 64; k++) {
        float a = __shfl_sync(0xffffffffu, (k < 32) ? a20 : a21, k & 31);
        o20 += a * sW2[lane * 65 + k];
        o21 += a * sW2[(lane + 32) * 65 + k];
    }
    float v0 = 0.5f * (lrelu(o10) + lrelu(o20));
    float v1 = 0.5f * (lrelu(o11) + lrelu(o21));
    float ss = warpsum(v0 * v0 + v1 * v1);
    float inv = 1.f / fmaxf(sqrtf(ss), 1e-12f);
    v0 *= inv; v1 *= inv;
    entout[e * 64 + lane] = v0;
    entout[e * 64 + 32 + lane] = v1;
    out[e * 64 + lane] += v0;
    out[e * 64 + 32 + lane] += v1;
    if (eItem) {
        float dn = 1.f / fmaxf((float)n, 1.f);
        g_rel[e * 64 + lane] = ar0 * dn;
        g_rel[e * 64 + 32 + lane] = ar1 * dn;
    }
}

__global__ void k_relkg(const float* __restrict__ ext_ent, int hop) {
    const float* kgbase = hop ? g_entB : ext_ent;
    int i = blockIdx.x * blockDim.x + threadIdx.x;
    if (i < NI * DM) g_relkg[i] = g_rel[i] * kgbase[i];
}

__global__ void k_item(const float* __restrict__ ext_ucf, int hop,
                       const int* __restrict__ imat, float* __restrict__ out) {
    const float* ucfin = hop ? g_ucf0 : ext_ucf;
    float* icfout      = hop ? g_icf1 : g_icf0;
    int t = threadIdx.x, lane = t & 31;
    int c = blockIdx.x * (blockDim.x >> 5) + (t >> 5);
    if (c >= NI) return;
    int p0 = g_off[SEG_I + c], p1 = g_off[SEG_I + c + 1];
    float a0 = 0, a1 = 0;
    for (int p = p0; p < p1; p++) {
        int pid = g_perm[p];
        int row = imat[2 * pid];
        a0 += ucfin[row * 64 + lane];
        a1 += ucfin[row * 64 + 32 + lane];
    }
    float dn = 1.f / fmaxf((float)(p1 - p0), 1.f);
    a0 *= dn; a1 *= dn;
    float ss = warpsum(a0 * a0 + a1 * a1);
    float inv = 1.f / fmaxf(sqrtf(ss), 1e-12f);
    a0 *= inv; a1 *= inv;
    icfout[c * 64 + lane] = a0;
    icfout[c * 64 + 32 + lane] = a1;
    const int ob = (NE + 2 * NU) * DM;
    out[ob + c * 64 + lane] += a0;
    out[ob + c * 64 + 32 + lane] += a1;
}

// fused user kernel: warp/user, oct-parallel dots (4 pairs in flight),
// smem-resident state, max-free softmax (shift-invariance, sigmoid bounded).
__global__ void __launch_bounds__(256) k_userhop(
        const float* __restrict__ ext_user, const float* __restrict__ ext_ucf,
        const float* __restrict__ ext_ent, const float* __restrict__ ext_icf,
        int hop, const int* __restrict__ imat, float* __restrict__ out)
{
    __shared__ __align__(16) float sm[8 * 320];   // per warp: U64|UC64|W64|WC64|COL64

    const float* kg   = hop ? g_entB : ext_ent;
    const float* icf  = hop ? g_icf0 : ext_icf;
    const float4* kg4  = (const float4*)kg;       // unused for dots; rk used instead
    const float4* rk4  = (const float4*)g_relkg;
    const float4* icf4 = (const float4*)icf;
    const float2* kg2  = (const float2*)kg;
    const float2* icf2 = (const float2*)icf;
    const float2* rk2  = (const float2*)g_relkg;
    const float* usrc   = hop ? g_u    : ext_user;
    const float* ucfsrc = hop ? g_ucf0 : ext_ucf;
    float2* udst2   = (float2*)g_u;
    float2* ucfdst2 = (float2*)(hop ? g_ucf1 : g_ucf0);
    float2* out2    = (float2*)out;
    (void)kg4;

    int w = threadIdx.x >> 5, lane = threadIdx.x & 31;
    int u = blockIdx.x * 8 + w;
    if (u >= NU) return;

    float* sU  = sm + w * 320;
    float* sUC = sU + 64;
    float* sW  = sU + 128;
    float* sWC = sU + 192;
    int*   sCol = (int*)(sU + 256);

    int p0 = g_off[SEG_U + u];
    int n  = g_off[SEG_U + u + 1] - p0;
    if (n == 0) {
        float2 z = make_float2(0.f, 0.f);
        udst2[u * 32 + lane] = z;
        ucfdst2[u * 32 + lane] = z;
        return;
    }
    int pb = p0 - NEDGE;
    int nin = n < 64 ? n : 64;

    sU[lane]       = usrc[u * 64 + lane];
    sU[32 + lane]  = usrc[u * 64 + 32 + lane];
    sUC[lane]      = ucfsrc[u * 64 + lane];
    sUC[32 + lane] = ucfsrc[u * 64 + 32 + lane];
    if (lane < nin)      sCol[lane]      = imat[2 * g_perm[p0 + lane] + 1];
    if (lane + 32 < nin) sCol[lane + 32] = imat[2 * g_perm[p0 + lane + 32] + 1];
    __syncwarp();

    float2 ud, cd;   // final result registers
    int li = lane & 7, g = lane >> 3;

    for (int it = 0; it < 3; it++) {
        // ---- pass 1: dots, 4 pairs per warp concurrently (8 lanes each) ----
        for (int jb = 0; jb < nin; jb += 4) {
            int j = jb + g;
            bool act = j < nin;
            int col = act ? sCol[j] : 0;
            float4 a0 = rk4[col * 16 + li],     a1 = rk4[col * 16 + 8 + li];
            float4 b0 = icf4[col * 16 + li],    b1 = icf4[col * 16 + 8 + li];
            float4 u0 = *(const float4*)(sU + 4 * li);
            float4 u1 = *(const float4*)(sU + 32 + 4 * li);
            float4 c0 = *(const float4*)(sUC + 4 * li);
            float4 c1 = *(const float4*)(sUC + 32 + 4 * li);
            float s  = a0.x*u0.x + a0.y*u0.y + a0.z*u0.z + a0.w*u0.w
                     + a1.x*u1.x + a1.y*u1.y + a1.z*u1.z + a1.w*u1.w;
            float sc = b0.x*c0.x + b0.y*c0.y + b0.z*c0.z + b0.w*c0.w
                     + b1.x*c1.x + b1.y*c1.y + b1.z*c1.z + b1.w*c1.w;
            s  += __shfl_xor_sync(0xffffffffu, s, 1);
            sc += __shfl_xor_sync(0xffffffffu, sc, 1);
            s  += __shfl_xor_sync(0xffffffffu, s, 2);
            sc += __shfl_xor_sync(0xffffffffu, sc, 2);
            s  += __shfl_xor_sync(0xffffffffu, s, 4);
            sc += __shfl_xor_sync(0xffffffffu, sc, 4);
            if (li == 0 && act) { sW[j] = s; sWC[j] = sc; }
        }
        for (int j = 64; j < n; j++) {   // fallback (not taken for this data)
            int col = imat[2 * g_perm[p0 + j] + 1];
            float2 rk = rk2[col * 32 + lane];
            float2 iv = icf2[col * 32 + lane];
            float s  = warpsum(rk.x * sU[2 * lane] + rk.y * sU[2 * lane + 1]);
            float sc = warpsum(iv.x * sUC[2 * lane] + iv.y * sUC[2 * lane + 1]);
            if (lane == 0) { g_p[pb + j] = s; g_pcf[pb + j] = sc; }
        }
        __syncwarp();
        // ---- pass 2: weights = exp(sigmoid(dot)) (max-free, exact) ----
        float se = 0.f, sec = 0.f;
        if (lane < nin) {
            float e  = __expf(sigmoidf(sW[lane]));
            float ec = __expf(sigmoidf(sWC[lane]));
            sW[lane] = e; sWC[lane] = ec; se += e; sec += ec;
        }
        if (lane + 32 < nin) {
            float e  = __expf(sigmoidf(sW[lane + 32]));
            float ec = __expf(sigmoidf(sWC[lane + 32]));
            sW[lane + 32] = e; sWC[lane + 32] = ec; se += e; sec += ec;
        }
        for (int j = 64 + lane; j < n; j += 32) {
            float e  = __expf(sigmoidf(g_p[pb + j]));
            float ec = __expf(sigmoidf(g_pcf[pb + j]));
            g_p[pb + j] = e; g_pcf[pb + j] = ec;
            se += e; sec += ec;
        }
        se = warpsum(se); sec = warpsum(sec);
        float inv = 1.f / se, invc = 1.f / sec;
        __syncwarp();
        // ---- pass 3: weighted accumulation ----
        float2 A = make_float2(0.f, 0.f), B = make_float2(0.f, 0.f);
        for (int j = 0; j < nin; j++) {
            int col = sCol[j];
            float wp = sW[j] * inv, wc = sWC[j] * invc;
            float2 gv = kg2[col * 32 + lane];
            float2 iv = icf2[col * 32 + lane];
            A.x += wp * gv.x; A.y += wp * gv.y;
            B.x += wc * iv.x; B.y += wc * iv.y;
        }
        for (int j = 64; j < n; j++) {
            float wp = g_p[pb + j] * inv, wc = g_pcf[pb + j] * invc;
            int col = imat[2 * g_perm[p0 + j] + 1];
            float2 gv = kg2[col * 32 + lane];
            float2 iv = icf2[col * 32 + lane];
            A.x += wp * gv.x; A.y += wp * gv.y;
            B.x += wc * iv.x; B.y += wc * iv.y;
        }
        float ss = warpsum(A.x * A.x + A.y * A.y);
        float i1 = 1.f / fmaxf(sqrtf(ss), 1e-12f);
        ss = warpsum(B.x * B.x + B.y * B.y);
        float i2 = 1.f / fmaxf(sqrtf(ss), 1e-12f);
        ud.x = A.x * i1; ud.y = A.y * i1;
        cd.x = B.x * i2; cd.y = B.y * i2;
        if (it < 2) {
            __syncwarp();
            sU[2 * lane] = ud.x;  sU[2 * lane + 1] = ud.y;
            sUC[2 * lane] = cd.x; sUC[2 * lane + 1] = cd.y;
            __syncwarp();
        }
    }

    udst2[u * 32 + lane] = ud;
    ucfdst2[u * 32 + lane] = cd;
    int o1 = NE * 32 + u * 32 + lane;
    float2 o = out2[o1]; o.x += ud.x; o.y += ud.y; out2[o1] = o;
    int o2 = (NE + NU) * 32 + u * 32 + lane;
    o = out2[o2]; o.x += cd.x; o.y += cd.y; out2[o2] = o;
}

extern "C" void kernel_launch(void* const* d_in, const int* in_sizes, int n_in,
                              void* d_out, int out_size) {
    const float* user_emb = (const float*)d_in[0];
    const float* entity_emb = (const float*)d_in[1];
    const float* emb_cf = (const float*)d_in[2];
    const float* relw = (const float*)d_in[3];
    const float* W1 = (const float*)d_in[4];
    const float* B1 = (const float*)d_in[5];
    const float* W2 = (const float*)d_in[6];
    const float* B2 = (const float*)d_in[7];
    const int* eidx = (const int*)d_in[8];
    const int* etype = (const int*)d_in[9];
    const int* imat = (const int*)d_in[10];
    float* out = (float*)d_out;

    const int* heads = eidx;
    const int* tails = eidx + NEDGE;
    const float* ucf_ext = emb_cf;
    const float* icf_ext = emb_cf + NU * DM;

    k_init<<<2048, 256>>>(user_emb, entity_emb, emb_cf, out);
    k_zero<<<1056, 256>>>();
    k_count<<<3907, 256>>>(heads, imat);
    k_scan1<<<SCAN_NBLK, SCAN_BLK>>>();
    k_scan2<<<1, SCAN_BLK>>>();
    k_scan3<<<SCAN_NBLK, SCAN_BLK>>>();
    k_scatter<<<3907, 256>>>(heads, imat);

    for (int h = 0; h < 2; h++) {
        k_entity<<<NE / 8, 256>>>(entity_emb, h, relw,
                                  W1 + h * DM * DM, B1 + h * DM,
                                  W2 + h * DM * DM, B2 + h * DM,
                                  tails, etype, out);
        k_relkg<<<(NI * DM + 255) / 256, 256>>>(entity_emb, h);
        k_item<<<NI / 8, 256>>>(ucf_ext, h, imat, out);
        k_userhop<<<(NU + 7) / 8, 256>>>(user_emb, ucf_ext, entity_emb, icf_ext,
                                         h, imat, out);
    }
    (void)in_sizes; (void)n_in; (void)out_size;
}